// round 2
// baseline (speedup 1.0000x reference)
#include <cuda_runtime.h>

#define Nn   512
#define Vv   3889
#define Jj   35
#define NBb  20
#define PF   306
#define KTOT 326          // NBb + PF
#define VC   11667        // Vv*3
#define NJ3  105          // Jj*3

#define JOINTS_OFF (Nn*VC)               // 5973504
#define RS_OFF     (JOINTS_OFF + Nn*NJ3) // 6027264

typedef unsigned long long ull;

// ---------------- f32x2 packed-math helpers (sm_103a) ------------------------
__device__ __forceinline__ ull pack2(float lo, float hi) {
    ull r; asm("mov.b64 %0, {%1,%2};" : "=l"(r) : "f"(lo), "f"(hi)); return r;
}
__device__ __forceinline__ void unpack2(ull v, float& lo, float& hi) {
    asm("mov.b64 {%0,%1}, %2;" : "=f"(lo), "=f"(hi) : "l"(v));
}
__device__ __forceinline__ void fma2(ull& d, ull a, ull b) {
    asm("fma.rn.f32x2 %0, %1, %2, %0;" : "+l"(d) : "l"(a), "l"(b));
}

// ---------------- scratch (static device globals; no runtime alloc) -----------
__device__ float g_pf[Nn*PF];        // pose feature (Rs[:,1:]-I) flattened
__device__ float g_vshaped[Nn*VC];
__device__ float g_vposed[Nn*VC];
__device__ float g_JrT[Jj*Vv];       // J_regressor transposed [j][v]
__device__ float g_WtT[Jj*Vv];       // weights transposed [j][v]
__device__ float g_Jp[Nn*NJ3];       // joints of v_shaped
__device__ float g_part[Nn*8*NJ3];   // split-V reduction partials
__device__ float g_A[Nn*Jj*12];      // 3x4 skinning transforms

// ---------------- K1: transpose J_regressor and weights ----------------------
__global__ void k_transpose(const float* __restrict__ Jr, const float* __restrict__ Wt) {
    int i = blockIdx.x * 256 + threadIdx.x;
    const int tot = Jj * Vv;
    if (i < tot) {
        int j = i / Vv, v = i % Vv;
        g_JrT[i] = Jr[v * Jj + j];
    } else if (i < 2 * tot) {
        int k = i - tot;
        int j = k / Vv, v = k % Vv;
        g_WtT[k] = Wt[v * Jj + j];
    }
}

// ---------------- K2: Rodrigues + pose feature --------------------------------
__global__ void k_rodrigues(const float* __restrict__ theta, float* __restrict__ rs_out) {
    int idx = blockIdx.x * 128 + threadIdx.x;
    if (idx >= Nn * Jj) return;
    int n = idx / Jj, j = idx % Jj;
    const float* th = theta + n * NJ3 + j * 3;
    float x = th[0], y = th[1], z = th[2];
    float ang = sqrtf(x * x + y * y + z * z + 1e-8f);
    float inv = 1.0f / ang;
    float rx = x * inv, ry = y * inv, rz = z * inv;
    float c = cosf(ang), s = sinf(ang);
    float ic = 1.0f - c;
    float R[9];
    R[0] = c + ic * rx * rx;  R[1] = ic * rx * ry - s * rz; R[2] = ic * rx * rz + s * ry;
    R[3] = ic * ry * rx + s * rz; R[4] = c + ic * ry * ry;  R[5] = ic * ry * rz - s * rx;
    R[6] = ic * rz * rx - s * ry; R[7] = ic * rz * ry + s * rx; R[8] = c + ic * rz * rz;
    float* ro = rs_out + (n * Jj + j) * 9;
    #pragma unroll
    for (int e = 0; e < 9; e++) ro[e] = R[e];
    if (j > 0) {
        float* pf = g_pf + n * PF + (j - 1) * 9;
        #pragma unroll
        for (int e = 0; e < 9; e++) pf[e] = R[e] - ((e == 0 || e == 4 || e == 8) ? 1.0f : 0.0f);
    }
}

// ---------------- K3: fused shape+pose GEMM (f32x2 packed) --------------------
// C[n, vc] = [beta | pf][n, 0:326] @ [shapedirs; posedirs][0:326, vc]
// 32 batch rows x 512 cols per block; 256 threads; 2 cols/thread; rows packed
// in pairs inside f32x2 lanes. B loads double-buffered.
__global__ void __launch_bounds__(256) k_gemm(
        const float* __restrict__ beta, const float* __restrict__ vtemp,
        const float* __restrict__ deform, const float* __restrict__ sdirs,
        const float* __restrict__ pdirs) {
    __shared__ __align__(16) float As[KTOT * 32];  // [k][r], r contiguous
    const int t = threadIdx.x;
    const int nb = blockIdx.y * 32;
    for (int i = t; i < KTOT * 32; i += 256) {
        int k = i >> 5, r = i & 31, n = nb + r;
        As[i] = (k < NBb) ? beta[n * NBb + k] : g_pf[n * PF + (k - NBb)];
    }
    __syncthreads();

    const int c0 = blockIdx.x * 512 + t;
    const int c1 = c0 + 256;
    const bool ok0 = c0 < VC, ok1 = c1 < VC;

    ull acc[16][2];
    #pragma unroll
    for (int rp = 0; rp < 16; rp++) { acc[rp][0] = 0ull; acc[rp][1] = 0ull; }

    // phase 1: shape (k < 20)
    float b0 = ok0 ? sdirs[c0] : 0.f;
    float b1 = ok1 ? sdirs[c1] : 0.f;
    for (int k = 0; k < NBb; k++) {
        ull B0 = pack2(b0, b0), B1 = pack2(b1, b1);
        float p0 = 0.f, p1 = 0.f;
        if (k + 1 < NBb) {
            p0 = ok0 ? sdirs[(k + 1) * VC + c0] : 0.f;
            p1 = ok1 ? sdirs[(k + 1) * VC + c1] : 0.f;
        }
        const ull* A2 = (const ull*)(As + k * 32);
        #pragma unroll
        for (int rp = 0; rp < 16; rp++) {
            ull a = A2[rp];
            fma2(acc[rp][0], a, B0);
            fma2(acc[rp][1], a, B1);
        }
        b0 = p0; b1 = p1;
    }

    // mid: add template + deform, emit v_shaped, keep running in acc
    {
        float vt0 = ok0 ? vtemp[c0] : 0.f;
        float vt1 = ok1 ? vtemp[c1] : 0.f;
        #pragma unroll
        for (int rp = 0; rp < 16; rp++) {
            float lo, hi;
            unpack2(acc[rp][0], lo, hi);
            if (ok0) {
                lo += vt0 + deform[(nb + 2 * rp)     * VC + c0];
                hi += vt0 + deform[(nb + 2 * rp + 1) * VC + c0];
                g_vshaped[(nb + 2 * rp)     * VC + c0] = lo;
                g_vshaped[(nb + 2 * rp + 1) * VC + c0] = hi;
            }
            acc[rp][0] = pack2(lo, hi);
            unpack2(acc[rp][1], lo, hi);
            if (ok1) {
                lo += vt1 + deform[(nb + 2 * rp)     * VC + c1];
                hi += vt1 + deform[(nb + 2 * rp + 1) * VC + c1];
                g_vshaped[(nb + 2 * rp)     * VC + c1] = lo;
                g_vshaped[(nb + 2 * rp + 1) * VC + c1] = hi;
            }
            acc[rp][1] = pack2(lo, hi);
        }
    }

    // phase 2: pose (k in [0,306))
    b0 = ok0 ? pdirs[c0] : 0.f;
    b1 = ok1 ? pdirs[c1] : 0.f;
    for (int k = 0; k < PF; k++) {
        ull B0 = pack2(b0, b0), B1 = pack2(b1, b1);
        float p0 = 0.f, p1 = 0.f;
        if (k + 1 < PF) {
            p0 = ok0 ? pdirs[(k + 1) * VC + c0] : 0.f;
            p1 = ok1 ? pdirs[(k + 1) * VC + c1] : 0.f;
        }
        const ull* A2 = (const ull*)(As + (k + NBb) * 32);
        #pragma unroll
        for (int rp = 0; rp < 16; rp++) {
            ull a = A2[rp];
            fma2(acc[rp][0], a, B0);
            fma2(acc[rp][1], a, B1);
        }
        b0 = p0; b1 = p1;
    }

    // epilogue: write v_posed
    #pragma unroll
    for (int rp = 0; rp < 16; rp++) {
        float lo, hi;
        unpack2(acc[rp][0], lo, hi);
        if (ok0) {
            g_vposed[(nb + 2 * rp)     * VC + c0] = lo;
            g_vposed[(nb + 2 * rp + 1) * VC + c0] = hi;
        }
        unpack2(acc[rp][1], lo, hi);
        if (ok1) {
            g_vposed[(nb + 2 * rp)     * VC + c1] = lo;
            g_vposed[(nb + 2 * rp + 1) * VC + c1] = hi;
        }
    }
}

// ---------------- K4: J-regressor reduce, smem-tiled batched GEMM -------------
// Out[n,j,c] = sum_v X[n,v,c] * Jr[v,j]. Block: 32 n x 35 j, 288 threads.
// Thread owns (n_local, 4 consecutive j). Partials over 8 V-splits.
__global__ void __launch_bounds__(288) k_reduce_part(int mode, const float* __restrict__ Xext) {
    const float* X = mode ? Xext : g_vshaped;
    __shared__ __align__(16) float sX[32 * 128];  // [v][n*4+c], c padded to 4
    __shared__ __align__(16) float sJ[32 * 36];   // [v][j], j padded to 36
    const int t = threadIdx.x;
    const int nb = blockIdx.y * 32;
    const int ch = blockIdx.x;
    int v0 = ch * 487, v1 = v0 + 487; if (v1 > Vv) v1 = Vv;
    const int n_l = t / 9, jq = t % 9;

    float acc[4][3];
    #pragma unroll
    for (int i = 0; i < 4; i++)
        #pragma unroll
        for (int c = 0; c < 3; c++) acc[i][c] = 0.f;

    for (int vb = v0; vb < v1; vb += 32) {
        int vn = v1 - vb; if (vn > 32) vn = 32;
        __syncthreads();
        const int tot = vn * 3;
        for (int i = t; i < 32 * tot; i += 288) {
            int nl = i / tot, rem = i - nl * tot;
            int vl = rem / 3, c = rem - vl * 3;
            sX[vl * 128 + nl * 4 + c] = X[(nb + nl) * VC + vb * 3 + rem];
        }
        for (int i = t; i < 35 * 32; i += 288) {
            int j = i >> 5, vl = i & 31;
            sJ[vl * 36 + j] = (vl < vn) ? g_JrT[j * Vv + vb + vl] : 0.f;
        }
        __syncthreads();
        for (int vl = 0; vl < vn; vl++) {
            float x0 = sX[vl * 128 + n_l * 4 + 0];
            float x1 = sX[vl * 128 + n_l * 4 + 1];
            float x2 = sX[vl * 128 + n_l * 4 + 2];
            float4 jr = *(const float4*)(sJ + vl * 36 + jq * 4);
            acc[0][0] = fmaf(jr.x, x0, acc[0][0]); acc[0][1] = fmaf(jr.x, x1, acc[0][1]); acc[0][2] = fmaf(jr.x, x2, acc[0][2]);
            acc[1][0] = fmaf(jr.y, x0, acc[1][0]); acc[1][1] = fmaf(jr.y, x1, acc[1][1]); acc[1][2] = fmaf(jr.y, x2, acc[1][2]);
            acc[2][0] = fmaf(jr.z, x0, acc[2][0]); acc[2][1] = fmaf(jr.z, x1, acc[2][1]); acc[2][2] = fmaf(jr.z, x2, acc[2][2]);
            acc[3][0] = fmaf(jr.w, x0, acc[3][0]); acc[3][1] = fmaf(jr.w, x1, acc[3][1]); acc[3][2] = fmaf(jr.w, x2, acc[3][2]);
        }
    }
    const int n = nb + n_l;
    #pragma unroll
    for (int i = 0; i < 4; i++) {
        int j = jq * 4 + i;
        if (j < Jj) {
            float* dst = g_part + (size_t)(n * 8 + ch) * NJ3 + j * 3;
            dst[0] = acc[i][0]; dst[1] = acc[i][1]; dst[2] = acc[i][2];
        }
    }
}

__global__ void k_reduce_final(int mode, float* __restrict__ dstext) {
    int i = blockIdx.x * 128 + threadIdx.x;
    if (i >= Nn * NJ3) return;
    int n = i / NJ3;
    float s = 0.0f;
    #pragma unroll
    for (int ch = 0; ch < 8; ch++) s += g_part[(size_t)(n * 8 + ch) * NJ3 + (i % NJ3)];
    if (mode == 0) g_Jp[i] = s; else dstext[i] = s;
}

// ---------------- K5: kinematic chain (thread per batch element) --------------
__global__ void k_kin(const float* __restrict__ rs, const float* __restrict__ scales,
                      const int* __restrict__ parents) {
    int n = blockIdx.x * 128 + threadIdx.x;
    if (n >= Nn) return;
    const float* R  = rs + n * Jj * 9;
    const float* Jp = g_Jp + n * NJ3;
    const float* sc = scales + n * NJ3;
    float G[Jj][12];
    #pragma unroll
    for (int a = 0; a < 3; a++) {
        G[0][a * 4 + 0] = R[a * 3 + 0];
        G[0][a * 4 + 1] = R[a * 3 + 1];
        G[0][a * 4 + 2] = R[a * 3 + 2];
        G[0][a * 4 + 3] = Jp[a];
    }
    for (int i = 1; i < Jj; i++) {
        int p = parents[i];
        float si0 = sc[i * 3 + 0], si1 = sc[i * 3 + 1], si2 = sc[i * 3 + 2];
        float ip0 = 1.0f / sc[p * 3 + 0], ip1 = 1.0f / sc[p * 3 + 1], ip2 = 1.0f / sc[p * 3 + 2];
        float rot[3][3];
        const float* Ri = R + i * 9;
        rot[0][0] = Ri[0] * si0 * ip0; rot[0][1] = Ri[1] * si1 * ip0; rot[0][2] = Ri[2] * si2 * ip0;
        rot[1][0] = Ri[3] * si0 * ip1; rot[1][1] = Ri[4] * si1 * ip1; rot[1][2] = Ri[5] * si2 * ip1;
        rot[2][0] = Ri[6] * si0 * ip2; rot[2][1] = Ri[7] * si1 * ip2; rot[2][2] = Ri[8] * si2 * ip2;
        float t0 = Jp[i * 3 + 0] - Jp[p * 3 + 0];
        float t1 = Jp[i * 3 + 1] - Jp[p * 3 + 1];
        float t2 = Jp[i * 3 + 2] - Jp[p * 3 + 2];
        #pragma unroll
        for (int a = 0; a < 3; a++) {
            float g0 = G[p][a * 4 + 0], g1 = G[p][a * 4 + 1], g2 = G[p][a * 4 + 2], g3 = G[p][a * 4 + 3];
            G[i][a * 4 + 0] = g0 * rot[0][0] + g1 * rot[1][0] + g2 * rot[2][0];
            G[i][a * 4 + 1] = g0 * rot[0][1] + g1 * rot[1][1] + g2 * rot[2][1];
            G[i][a * 4 + 2] = g0 * rot[0][2] + g1 * rot[1][2] + g2 * rot[2][2];
            G[i][a * 4 + 3] = g0 * t0 + g1 * t1 + g2 * t2 + g3;
        }
    }
    float* gA = g_A + n * Jj * 12;
    for (int i = 0; i < Jj; i++) {
        float jx = Jp[i * 3 + 0], jy = Jp[i * 3 + 1], jz = Jp[i * 3 + 2];
        #pragma unroll
        for (int a = 0; a < 3; a++) {
            float g0 = G[i][a * 4 + 0], g1 = G[i][a * 4 + 1], g2 = G[i][a * 4 + 2];
            gA[i * 12 + a * 4 + 0] = g0;
            gA[i * 12 + a * 4 + 1] = g1;
            gA[i * 12 + a * 4 + 2] = g2;
            gA[i * 12 + a * 4 + 3] = G[i][a * 4 + 3] - (g0 * jx + g1 * jy + g2 * jz);
        }
    }
}

// ---------------- K6: skinning (f32x2 packed, 2 n per block) -------------------
__global__ void __launch_bounds__(128) k_skin(const float* __restrict__ trans, float* __restrict__ out) {
    __shared__ __align__(16) float sA[2 * Jj * 12];  // 840 floats
    const int t = threadIdx.x;
    const int nb = blockIdx.y * 2;
    for (int i = t; i < 2 * Jj * 12; i += 128) sA[i] = g_A[nb * Jj * 12 + i];
    __syncthreads();
    const ull* sA2 = (const ull*)sA;  // [nl*210 + j*6 + e]
    const int vb = blockIdx.x * 512 + t;

    ull T[2][4][6];
    #pragma unroll
    for (int nl = 0; nl < 2; nl++)
        #pragma unroll
        for (int u = 0; u < 4; u++)
            #pragma unroll
            for (int e = 0; e < 6; e++) T[nl][u][e] = 0ull;

    for (int j = 0; j < Jj; j++) {
        ull W[4];
        #pragma unroll
        for (int u = 0; u < 4; u++) {
            int v = vb + 128 * u;
            float w = (v < Vv) ? g_WtT[j * Vv + v] : 0.f;
            W[u] = pack2(w, w);
        }
        #pragma unroll
        for (int nl = 0; nl < 2; nl++) {
            #pragma unroll
            for (int e = 0; e < 6; e++) {
                ull a2 = sA2[nl * 210 + j * 6 + e];
                #pragma unroll
                for (int u = 0; u < 4; u++) fma2(T[nl][u][e], W[u], a2);
            }
        }
    }

    #pragma unroll
    for (int nl = 0; nl < 2; nl++) {
        int n = nb + nl;
        float t0 = trans[n * 3 + 0], t1 = trans[n * 3 + 1], t2 = trans[n * 3 + 2];
        #pragma unroll
        for (int u = 0; u < 4; u++) {
            int v = vb + 128 * u;
            if (v < Vv) {
                float e[12];
                #pragma unroll
                for (int p = 0; p < 6; p++) unpack2(T[nl][u][p], e[2 * p], e[2 * p + 1]);
                float x = g_vposed[n * VC + v * 3 + 0];
                float y = g_vposed[n * VC + v * 3 + 1];
                float z = g_vposed[n * VC + v * 3 + 2];
                out[n * VC + v * 3 + 0] = fmaf(e[0], x, fmaf(e[1], y, fmaf(e[2],  z, e[3])))  + t0;
                out[n * VC + v * 3 + 1] = fmaf(e[4], x, fmaf(e[5], y, fmaf(e[6],  z, e[7])))  + t1;
                out[n * VC + v * 3 + 2] = fmaf(e[8], x, fmaf(e[9], y, fmaf(e[10], z, e[11]))) + t2;
            }
        }
    }
}

// ---------------- launch -------------------------------------------------------
extern "C" void kernel_launch(void* const* d_in, const int* in_sizes, int n_in,
                              void* d_out, int out_size) {
    const float* beta     = (const float*)d_in[0];
    const float* theta    = (const float*)d_in[1];
    const float* scales   = (const float*)d_in[2];
    const float* deform   = (const float*)d_in[3];
    const float* trans    = (const float*)d_in[4];
    const float* vtemp    = (const float*)d_in[5];
    const float* sdirs    = (const float*)d_in[6];
    const float* pdirs    = (const float*)d_in[7];
    const float* Jr       = (const float*)d_in[8];
    const float* Wt       = (const float*)d_in[9];
    const int*   parents  = (const int*)d_in[10];
    float* out = (float*)d_out;

    k_transpose<<<(2 * Jj * Vv + 255) / 256, 256>>>(Jr, Wt);
    k_rodrigues<<<(Nn * Jj + 127) / 128, 128>>>(theta, out + RS_OFF);
    k_gemm<<<dim3(23, 16), 256>>>(beta, vtemp, deform, sdirs, pdirs);
    k_reduce_part<<<dim3(8, 16), 288>>>(0, nullptr);
    k_reduce_final<<<(Nn * NJ3 + 127) / 128, 128>>>(0, nullptr);
    k_kin<<<(Nn + 127) / 128, 128>>>(out + RS_OFF, scales, parents);
    k_skin<<<dim3(8, 256), 128>>>(trans, out);
    k_reduce_part<<<dim3(8, 16), 288>>>(1, out);
    k_reduce_final<<<(Nn * NJ3 + 127) / 128, 128>>>(1, out + JOINTS_OFF);
}

// round 3
// speedup vs baseline: 1.4694x; 1.4694x over previous
#include <cuda_runtime.h>

#define Nn   512
#define Vv   3889
#define Jj   35
#define NBb  20
#define PF   306
#define KTOT 326          // NBb + PF
#define VC   11667        // Vv*3
#define NJ3  105          // Jj*3

#define JOINTS_OFF (Nn*VC)               // 5973504
#define RS_OFF     (JOINTS_OFF + Nn*NJ3) // 6027264

typedef unsigned long long ull;

// ---------------- f32x2 packed-math helpers (sm_103a) ------------------------
__device__ __forceinline__ ull pack2(float lo, float hi) {
    ull r; asm("mov.b64 %0, {%1,%2};" : "=l"(r) : "f"(lo), "f"(hi)); return r;
}
__device__ __forceinline__ void unpack2(ull v, float& lo, float& hi) {
    asm("mov.b64 {%0,%1}, %2;" : "=f"(lo), "=f"(hi) : "l"(v));
}
__device__ __forceinline__ void fma2(ull& d, ull a, ull b) {
    asm("fma.rn.f32x2 %0, %1, %2, %0;" : "+l"(d) : "l"(a), "l"(b));
}

// ---------------- scratch (static device globals) -----------------------------
__device__ float g_pf[Nn*PF];          // pose feature
__device__ float g_vshaped[Nn*3*Vv];   // SoA [n][c][v]
__device__ float g_vposed[Nn*3*Vv];    // SoA [n][c][v]
__device__ float g_vertsT[Nn*3*Vv];    // SoA copy of final verts
__device__ float g_JrT[Jj*Vv];         // J_regressor transposed [j][v]
__device__ float g_WtT[Jj*Vv];         // weights transposed [j][v]
__device__ float g_Jp[Nn*NJ3];
__device__ float g_part[Nn*8*NJ3];
__device__ float g_A[Nn*Jj*12];

// ---------------- K1: transpose J_regressor and weights ----------------------
__global__ void k_transpose(const float* __restrict__ Jr, const float* __restrict__ Wt) {
    int i = blockIdx.x * 256 + threadIdx.x;
    const int tot = Jj * Vv;
    if (i < tot) {
        int j = i / Vv, v = i % Vv;
        g_JrT[i] = Jr[v * Jj + j];
    } else if (i < 2 * tot) {
        int k = i - tot;
        int j = k / Vv, v = k % Vv;
        g_WtT[k] = Wt[v * Jj + j];
    }
}

// ---------------- K2: Rodrigues + pose feature --------------------------------
__global__ void k_rodrigues(const float* __restrict__ theta, float* __restrict__ rs_out) {
    int idx = blockIdx.x * 128 + threadIdx.x;
    if (idx >= Nn * Jj) return;
    int n = idx / Jj, j = idx % Jj;
    const float* th = theta + n * NJ3 + j * 3;
    float x = th[0], y = th[1], z = th[2];
    float ang = sqrtf(x * x + y * y + z * z + 1e-8f);
    float inv = 1.0f / ang;
    float rx = x * inv, ry = y * inv, rz = z * inv;
    float c = cosf(ang), s = sinf(ang);
    float ic = 1.0f - c;
    float R[9];
    R[0] = c + ic * rx * rx;  R[1] = ic * rx * ry - s * rz; R[2] = ic * rx * rz + s * ry;
    R[3] = ic * ry * rx + s * rz; R[4] = c + ic * ry * ry;  R[5] = ic * ry * rz - s * rx;
    R[6] = ic * rz * rx - s * ry; R[7] = ic * rz * ry + s * rx; R[8] = c + ic * rz * rz;
    float* ro = rs_out + (n * Jj + j) * 9;
    #pragma unroll
    for (int e = 0; e < 9; e++) ro[e] = R[e];
    if (j > 0) {
        float* pf = g_pf + n * PF + (j - 1) * 9;
        #pragma unroll
        for (int e = 0; e < 9; e++) pf[e] = R[e] - ((e == 0 || e == 4 || e == 8) ? 1.0f : 0.0f);
    }
}

// ---------------- K3: fused shape+pose GEMM (f32x2, SoA output) ---------------
__global__ void __launch_bounds__(256) k_gemm(
        const float* __restrict__ beta, const float* __restrict__ vtemp,
        const float* __restrict__ deform, const float* __restrict__ sdirs,
        const float* __restrict__ pdirs) {
    __shared__ __align__(16) float As[KTOT * 32];  // [k][r]
    const int t = threadIdx.x;
    const int nb = blockIdx.y * 32;
    for (int i = t; i < KTOT * 32; i += 256) {
        int k = i >> 5, r = i & 31, n = nb + r;
        As[i] = (k < NBb) ? beta[n * NBb + k] : g_pf[n * PF + (k - NBb)];
    }
    __syncthreads();

    const int c0 = blockIdx.x * 512 + t;
    const int c1 = c0 + 256;
    const bool ok0 = c0 < VC, ok1 = c1 < VC;
    const int vv0 = c0 / 3, cc0 = c0 - 3 * vv0;
    const int vv1 = c1 / 3, cc1 = c1 - 3 * vv1;

    ull acc[16][2];
    #pragma unroll
    for (int rp = 0; rp < 16; rp++) { acc[rp][0] = 0ull; acc[rp][1] = 0ull; }

    float b0 = ok0 ? sdirs[c0] : 0.f;
    float b1 = ok1 ? sdirs[c1] : 0.f;
    for (int k = 0; k < NBb; k++) {
        ull B0 = pack2(b0, b0), B1 = pack2(b1, b1);
        float p0 = 0.f, p1 = 0.f;
        if (k + 1 < NBb) {
            p0 = ok0 ? sdirs[(k + 1) * VC + c0] : 0.f;
            p1 = ok1 ? sdirs[(k + 1) * VC + c1] : 0.f;
        }
        const ull* A2 = (const ull*)(As + k * 32);
        #pragma unroll
        for (int rp = 0; rp < 16; rp++) {
            ull a = A2[rp];
            fma2(acc[rp][0], a, B0);
            fma2(acc[rp][1], a, B1);
        }
        b0 = p0; b1 = p1;
    }

    // mid: add template + deform, emit v_shaped (SoA), keep running
    {
        float vt0 = ok0 ? vtemp[c0] : 0.f;
        float vt1 = ok1 ? vtemp[c1] : 0.f;
        #pragma unroll
        for (int rp = 0; rp < 16; rp++) {
            float lo, hi;
            unpack2(acc[rp][0], lo, hi);
            if (ok0) {
                lo += vt0 + deform[(nb + 2 * rp)     * VC + c0];
                hi += vt0 + deform[(nb + 2 * rp + 1) * VC + c0];
                g_vshaped[(size_t)(nb + 2 * rp)     * 3 * Vv + cc0 * Vv + vv0] = lo;
                g_vshaped[(size_t)(nb + 2 * rp + 1) * 3 * Vv + cc0 * Vv + vv0] = hi;
            }
            acc[rp][0] = pack2(lo, hi);
            unpack2(acc[rp][1], lo, hi);
            if (ok1) {
                lo += vt1 + deform[(nb + 2 * rp)     * VC + c1];
                hi += vt1 + deform[(nb + 2 * rp + 1) * VC + c1];
                g_vshaped[(size_t)(nb + 2 * rp)     * 3 * Vv + cc1 * Vv + vv1] = lo;
                g_vshaped[(size_t)(nb + 2 * rp + 1) * 3 * Vv + cc1 * Vv + vv1] = hi;
            }
            acc[rp][1] = pack2(lo, hi);
        }
    }

    b0 = ok0 ? pdirs[c0] : 0.f;
    b1 = ok1 ? pdirs[c1] : 0.f;
    for (int k = 0; k < PF; k++) {
        ull B0 = pack2(b0, b0), B1 = pack2(b1, b1);
        float p0 = 0.f, p1 = 0.f;
        if (k + 1 < PF) {
            p0 = ok0 ? pdirs[(k + 1) * VC + c0] : 0.f;
            p1 = ok1 ? pdirs[(k + 1) * VC + c1] : 0.f;
        }
        const ull* A2 = (const ull*)(As + (k + NBb) * 32);
        #pragma unroll
        for (int rp = 0; rp < 16; rp++) {
            ull a = A2[rp];
            fma2(acc[rp][0], a, B0);
            fma2(acc[rp][1], a, B1);
        }
        b0 = p0; b1 = p1;
    }

    #pragma unroll
    for (int rp = 0; rp < 16; rp++) {
        float lo, hi;
        unpack2(acc[rp][0], lo, hi);
        if (ok0) {
            g_vposed[(size_t)(nb + 2 * rp)     * 3 * Vv + cc0 * Vv + vv0] = lo;
            g_vposed[(size_t)(nb + 2 * rp + 1) * 3 * Vv + cc0 * Vv + vv0] = hi;
        }
        unpack2(acc[rp][1], lo, hi);
        if (ok1) {
            g_vposed[(size_t)(nb + 2 * rp)     * 3 * Vv + cc1 * Vv + vv1] = lo;
            g_vposed[(size_t)(nb + 2 * rp + 1) * 3 * Vv + cc1 * Vv + vv1] = hi;
        }
    }
}

// ---------------- K4: J-regressor reduce (SoA input, 4 n packed) --------------
// Out[n,j,c] = sum_v X[n][c][v] * JrT[j][v]. Grid (8 chunks, 128 n-quads),
// block 128 = 4 warps; warp w owns 9 j's; lane strides v.
__global__ void __launch_bounds__(128) k_reduce_part(int mode) {
    const float* X = mode ? g_vertsT : g_vshaped;
    const int ch = blockIdx.x;
    const int n0 = blockIdx.y * 4;
    const int w = threadIdx.x >> 5, lane = threadIdx.x & 31;
    const int j0 = w * 9;
    const int nj = (Jj - j0 < 9) ? (Jj - j0) : 9;

    ull acc[2][9][3];
    #pragma unroll
    for (int pp = 0; pp < 2; pp++)
        #pragma unroll
        for (int jj = 0; jj < 9; jj++)
            #pragma unroll
            for (int c = 0; c < 3; c++) acc[pp][jj][c] = 0ull;

    int v0 = ch * 487, v1 = v0 + 487; if (v1 > Vv) v1 = Vv;
    const float* Xb = X + (size_t)n0 * 3 * Vv;

    for (int v = v0 + lane; v < v1; v += 32) {
        float jr[9];
        #pragma unroll
        for (int jj = 0; jj < 9; jj++) jr[jj] = (jj < nj) ? g_JrT[(j0 + jj) * Vv + v] : 0.f;
        ull xv[2][3];
        #pragma unroll
        for (int pp = 0; pp < 2; pp++)
            #pragma unroll
            for (int c = 0; c < 3; c++)
                xv[pp][c] = pack2(Xb[(size_t)(2 * pp) * 3 * Vv + c * Vv + v],
                                  Xb[(size_t)(2 * pp + 1) * 3 * Vv + c * Vv + v]);
        #pragma unroll
        for (int jj = 0; jj < 9; jj++) {
            ull jr2 = pack2(jr[jj], jr[jj]);
            #pragma unroll
            for (int pp = 0; pp < 2; pp++)
                #pragma unroll
                for (int c = 0; c < 3; c++) fma2(acc[pp][jj][c], jr2, xv[pp][c]);
        }
    }

    #pragma unroll
    for (int jj = 0; jj < 9; jj++) {
        if (jj >= nj) break;
        #pragma unroll
        for (int pp = 0; pp < 2; pp++) {
            #pragma unroll
            for (int c = 0; c < 3; c++) {
                float lo, hi;
                unpack2(acc[pp][jj][c], lo, hi);
                #pragma unroll
                for (int o = 16; o; o >>= 1) {
                    lo += __shfl_xor_sync(0xffffffffu, lo, o);
                    hi += __shfl_xor_sync(0xffffffffu, hi, o);
                }
                if (lane == 0) {
                    int na = n0 + 2 * pp, nb2 = na + 1;
                    g_part[(size_t)(na * 8 + ch) * NJ3 + (j0 + jj) * 3 + c] = lo;
                    g_part[(size_t)(nb2 * 8 + ch) * NJ3 + (j0 + jj) * 3 + c] = hi;
                }
            }
        }
    }
}

__global__ void k_reduce_final(int mode, float* __restrict__ dstext) {
    int i = blockIdx.x * 128 + threadIdx.x;
    if (i >= Nn * NJ3) return;
    int n = i / NJ3;
    float s = 0.0f;
    #pragma unroll
    for (int ch = 0; ch < 8; ch++) s += g_part[(size_t)(n * 8 + ch) * NJ3 + (i % NJ3)];
    if (mode == 0) g_Jp[i] = s; else dstext[i] = s;
}

// ---------------- K5: kinematic chain — warp per n, G in shared ---------------
__global__ void __launch_bounds__(256) k_kin(const float* __restrict__ rs,
                                             const float* __restrict__ scales,
                                             const int* __restrict__ parents) {
    __shared__ float sG[8][Jj][12];
    const int w = threadIdx.x >> 5, lane = threadIdx.x & 31;
    const int n = blockIdx.x * 8 + w;
    if (n >= Nn) return;
    const float* R  = rs + (size_t)n * Jj * 9;
    const float* Jp = g_Jp + n * NJ3;
    const float* sc = scales + n * NJ3;
    const int a = lane >> 2, u = lane & 3;

    if (lane < 12) sG[w][0][lane] = (u < 3) ? R[a * 3 + u] : Jp[a];
    __syncwarp();

    for (int i = 1; i < Jj; i++) {
        int p = parents[i];
        float val = 0.f;
        if (lane < 12) {
            float gp0 = sG[w][p][a * 4 + 0];
            float gp1 = sG[w][p][a * 4 + 1];
            float gp2 = sG[w][p][a * 4 + 2];
            if (u < 3) {
                float si = sc[i * 3 + u];
                val = gp0 * (R[i * 9 + 0 + u] * si / sc[p * 3 + 0])
                    + gp1 * (R[i * 9 + 3 + u] * si / sc[p * 3 + 1])
                    + gp2 * (R[i * 9 + 6 + u] * si / sc[p * 3 + 2]);
            } else {
                float t0 = Jp[i * 3 + 0] - Jp[p * 3 + 0];
                float t1 = Jp[i * 3 + 1] - Jp[p * 3 + 1];
                float t2 = Jp[i * 3 + 2] - Jp[p * 3 + 2];
                val = gp0 * t0 + gp1 * t1 + gp2 * t2 + sG[w][p][a * 4 + 3];
            }
        }
        __syncwarp();
        if (lane < 12) sG[w][i][lane] = val;
        __syncwarp();
    }

    float* gA = g_A + (size_t)n * Jj * 12;
    for (int idx = lane; idx < Jj * 12; idx += 32) {
        int i = idx / 12, e = idx - i * 12;
        int aa = e >> 2, uu = e & 3;
        float val;
        if (uu < 3) val = sG[w][i][aa * 4 + uu];
        else {
            float g0 = sG[w][i][aa * 4 + 0], g1 = sG[w][i][aa * 4 + 1], g2 = sG[w][i][aa * 4 + 2];
            val = sG[w][i][aa * 4 + 3] - (g0 * Jp[i * 3 + 0] + g1 * Jp[i * 3 + 1] + g2 * Jp[i * 3 + 2]);
        }
        gA[idx] = val;
    }
}

// ---------------- K6: skinning (f32x2, SoA in, AoS out + SoA copy) ------------
__global__ void __launch_bounds__(128) k_skin(const float* __restrict__ trans, float* __restrict__ out) {
    __shared__ __align__(16) float sA[2 * Jj * 12];
    const int t = threadIdx.x;
    const int nb = blockIdx.y * 2;
    for (int i = t; i < 2 * Jj * 12; i += 128) sA[i] = g_A[(size_t)nb * Jj * 12 + i];
    __syncthreads();
    const ull* sA2 = (const ull*)sA;
    const int vb = blockIdx.x * 512 + t;

    ull T[2][4][6];
    #pragma unroll
    for (int nl = 0; nl < 2; nl++)
        #pragma unroll
        for (int u = 0; u < 4; u++)
            #pragma unroll
            for (int e = 0; e < 6; e++) T[nl][u][e] = 0ull;

    for (int j = 0; j < Jj; j++) {
        ull W[4];
        #pragma unroll
        for (int u = 0; u < 4; u++) {
            int v = vb + 128 * u;
            float w = (v < Vv) ? g_WtT[j * Vv + v] : 0.f;
            W[u] = pack2(w, w);
        }
        #pragma unroll
        for (int nl = 0; nl < 2; nl++) {
            #pragma unroll
            for (int e = 0; e < 6; e++) {
                ull a2 = sA2[nl * 210 + j * 6 + e];
                #pragma unroll
                for (int u = 0; u < 4; u++) fma2(T[nl][u][e], W[u], a2);
            }
        }
    }

    #pragma unroll
    for (int nl = 0; nl < 2; nl++) {
        int n = nb + nl;
        float t0 = trans[n * 3 + 0], t1 = trans[n * 3 + 1], t2 = trans[n * 3 + 2];
        const float* vp = g_vposed + (size_t)n * 3 * Vv;
        float* vt = g_vertsT + (size_t)n * 3 * Vv;
        #pragma unroll
        for (int u = 0; u < 4; u++) {
            int v = vb + 128 * u;
            if (v < Vv) {
                float e[12];
                #pragma unroll
                for (int p = 0; p < 6; p++) unpack2(T[nl][u][p], e[2 * p], e[2 * p + 1]);
                float x = vp[v], y = vp[Vv + v], z = vp[2 * Vv + v];
                float o0 = fmaf(e[0], x, fmaf(e[1], y, fmaf(e[2],  z, e[3])))  + t0;
                float o1 = fmaf(e[4], x, fmaf(e[5], y, fmaf(e[6],  z, e[7])))  + t1;
                float o2 = fmaf(e[8], x, fmaf(e[9], y, fmaf(e[10], z, e[11]))) + t2;
                out[(size_t)n * VC + v * 3 + 0] = o0;
                out[(size_t)n * VC + v * 3 + 1] = o1;
                out[(size_t)n * VC + v * 3 + 2] = o2;
                vt[v] = o0; vt[Vv + v] = o1; vt[2 * Vv + v] = o2;
            }
        }
    }
}

// ---------------- launch -------------------------------------------------------
extern "C" void kernel_launch(void* const* d_in, const int* in_sizes, int n_in,
                              void* d_out, int out_size) {
    const float* beta     = (const float*)d_in[0];
    const float* theta    = (const float*)d_in[1];
    const float* scales   = (const float*)d_in[2];
    const float* deform   = (const float*)d_in[3];
    const float* trans    = (const float*)d_in[4];
    const float* vtemp    = (const float*)d_in[5];
    const float* sdirs    = (const float*)d_in[6];
    const float* pdirs    = (const float*)d_in[7];
    const float* Jr       = (const float*)d_in[8];
    const float* Wt       = (const float*)d_in[9];
    const int*   parents  = (const int*)d_in[10];
    float* out = (float*)d_out;

    k_transpose<<<(2 * Jj * Vv + 255) / 256, 256>>>(Jr, Wt);
    k_rodrigues<<<(Nn * Jj + 127) / 128, 128>>>(theta, out + RS_OFF);
    k_gemm<<<dim3(23, 16), 256>>>(beta, vtemp, deform, sdirs, pdirs);
    k_reduce_part<<<dim3(8, 128), 128>>>(0);
    k_reduce_final<<<(Nn * NJ3 + 127) / 128, 128>>>(0, nullptr);
    k_kin<<<64, 256>>>(out + RS_OFF, scales, parents);
    k_skin<<<dim3(8, 256), 128>>>(trans, out);
    k_reduce_part<<<dim3(8, 128), 128>>>(1);
    k_reduce_final<<<(Nn * NJ3 + 127) / 128, 128>>>(1, out + JOINTS_OFF);
}

// round 4
// speedup vs baseline: 1.7056x; 1.1608x over previous
#include <cuda_runtime.h>

#define Nn   512
#define Vv   3889
#define Jj   35
#define NBb  20
#define PF   306
#define KTOT 326          // NBb + PF
#define VC   11667        // Vv*3
#define NJ3  105          // Jj*3
#define BW   11776        // padded B row stride (= 23*512, 16B-aligned)

#define JOINTS_OFF (Nn*VC)
#define RS_OFF     (JOINTS_OFF + Nn*NJ3)

typedef unsigned long long ull;

// ---------------- f32x2 packed-math helpers (sm_103a) ------------------------
__device__ __forceinline__ ull pack2(float lo, float hi) {
    ull r; asm("mov.b64 %0, {%1,%2};" : "=l"(r) : "f"(lo), "f"(hi)); return r;
}
__device__ __forceinline__ void unpack2(ull v, float& lo, float& hi) {
    asm("mov.b64 {%0,%1}, %2;" : "=f"(lo), "=f"(hi) : "l"(v));
}
__device__ __forceinline__ void fma2(ull& d, ull a, ull b) {
    asm("fma.rn.f32x2 %0, %1, %2, %0;" : "+l"(d) : "l"(a), "l"(b));
}

// ---------------- scratch ------------------------------------------------------
__device__ float g_pf[Nn*PF];
__device__ float g_B[KTOT*BW];        // padded/aligned [shapedirs; posedirs]
__device__ float g_vshaped[Nn*VC];    // AoS
__device__ float g_vposed[Nn*VC];     // AoS
__device__ float g_JrT[Jj*Vv];
__device__ float g_WtT[Jj*Vv];
__device__ float g_Jp[Nn*NJ3];
__device__ float g_part[Nn*8*NJ3];
__device__ float g_A[Nn*Jj*12];

// ---------------- K0: prep — pad B, transpose Jr/Wt ---------------------------
__global__ void k_prep(const float* __restrict__ sdirs, const float* __restrict__ pdirs,
                       const float* __restrict__ Jr, const float* __restrict__ Wt) {
    const int TOT1 = KTOT * BW;
    const int TOTT = Jj * Vv;
    int i = blockIdx.x * 256 + threadIdx.x;
    if (i < TOT1) {
        int k = i / BW, c = i - k * BW;
        float v = 0.f;
        if (c < VC) v = (k < NBb) ? sdirs[k * VC + c] : pdirs[(k - NBb) * VC + c];
        g_B[i] = v;
    } else if (i < TOT1 + TOTT) {
        int r = i - TOT1;
        int j = r / Vv, v = r - j * Vv;
        g_JrT[r] = Jr[v * Jj + j];
    } else if (i < TOT1 + 2 * TOTT) {
        int r = i - TOT1 - TOTT;
        int j = r / Vv, v = r - j * Vv;
        g_WtT[r] = Wt[v * Jj + j];
    }
}

// ---------------- K2: Rodrigues + pose feature --------------------------------
__global__ void k_rodrigues(const float* __restrict__ theta, float* __restrict__ rs_out) {
    int idx = blockIdx.x * 128 + threadIdx.x;
    if (idx >= Nn * Jj) return;
    int n = idx / Jj, j = idx % Jj;
    const float* th = theta + n * NJ3 + j * 3;
    float x = th[0], y = th[1], z = th[2];
    float ang = sqrtf(x * x + y * y + z * z + 1e-8f);
    float inv = 1.0f / ang;
    float rx = x * inv, ry = y * inv, rz = z * inv;
    float c = cosf(ang), s = sinf(ang);
    float ic = 1.0f - c;
    float R[9];
    R[0] = c + ic * rx * rx;  R[1] = ic * rx * ry - s * rz; R[2] = ic * rx * rz + s * ry;
    R[3] = ic * ry * rx + s * rz; R[4] = c + ic * ry * ry;  R[5] = ic * ry * rz - s * rx;
    R[6] = ic * rz * rx - s * ry; R[7] = ic * rz * ry + s * rx; R[8] = c + ic * rz * rz;
    float* ro = rs_out + (n * Jj + j) * 9;
    #pragma unroll
    for (int e = 0; e < 9; e++) ro[e] = R[e];
    if (j > 0) {
        float* pf = g_pf + n * PF + (j - 1) * 9;
        #pragma unroll
        for (int e = 0; e < 9; e++) pf[e] = R[e] - ((e == 0 || e == 4 || e == 8) ? 1.0f : 0.0f);
    }
}

// ---------------- K3: fused shape+pose GEMM (8 rows x 8 cols / thread) --------
__global__ void __launch_bounds__(256) k_gemm(
        const float* __restrict__ beta, const float* __restrict__ vtemp,
        const float* __restrict__ deform) {
    __shared__ __align__(16) float As[KTOT * 32];  // [k][row]
    const int t = threadIdx.x;
    const int nb = blockIdx.y * 32;
    for (int i = t; i < KTOT * 32; i += 256) {
        int k = i >> 5, r = i & 31, n = nb + r;
        As[i] = (k < NBb) ? beta[n * NBb + k] : g_pf[n * PF + (k - NBb)];
    }
    __syncthreads();

    const int ci = t & 63, ri = t >> 6;           // 64 col-threads x 4 row-threads
    const int cb0 = blockIdx.x * 512 + ci * 4;    // 16B aligned
    const int cb1 = cb0 + 256;

    ull acc[4][8];
    #pragma unroll
    for (int p = 0; p < 4; p++)
        #pragma unroll
        for (int q = 0; q < 8; q++) acc[p][q] = 0ull;

    float4 b0 = *(const float4*)(g_B + cb0);
    float4 b1 = *(const float4*)(g_B + cb1);

    // ---- phase 1: shape rows k in [0,20) ; prefetch flows into pose rows ----
    #pragma unroll 4
    for (int k = 0; k < NBb; k++) {
        float4 nb0 = *(const float4*)(g_B + (k + 1) * BW + cb0);
        float4 nb1 = *(const float4*)(g_B + (k + 1) * BW + cb1);
        const ull* A2 = (const ull*)(As + k * 32) + ri * 4;
        ull a[4] = {A2[0], A2[1], A2[2], A2[3]};
        ull B8[8] = {pack2(b0.x,b0.x), pack2(b0.y,b0.y), pack2(b0.z,b0.z), pack2(b0.w,b0.w),
                     pack2(b1.x,b1.x), pack2(b1.y,b1.y), pack2(b1.z,b1.z), pack2(b1.w,b1.w)};
        #pragma unroll
        for (int p = 0; p < 4; p++)
            #pragma unroll
            for (int q = 0; q < 8; q++) fma2(acc[p][q], a[p], B8[q]);
        b0 = nb0; b1 = nb1;
    }

    // ---- mid: + template + deform, emit v_shaped, keep accumulating ----
    {
        float vt[8];
        #pragma unroll
        for (int q = 0; q < 8; q++) {
            int c = (q < 4) ? cb0 + q : cb1 + q - 4;
            vt[q] = (c < VC) ? vtemp[c] : 0.f;
        }
        #pragma unroll
        for (int p = 0; p < 4; p++) {
            int ra = nb + 8 * ri + 2 * p, rb = ra + 1;
            #pragma unroll
            for (int q = 0; q < 8; q++) {
                int c = (q < 4) ? cb0 + q : cb1 + q - 4;
                float lo, hi;
                unpack2(acc[p][q], lo, hi);
                if (c < VC) {
                    lo += vt[q] + deform[(size_t)ra * VC + c];
                    hi += vt[q] + deform[(size_t)rb * VC + c];
                    g_vshaped[(size_t)ra * VC + c] = lo;
                    g_vshaped[(size_t)rb * VC + c] = hi;
                }
                acc[p][q] = pack2(lo, hi);
            }
        }
    }

    // ---- phase 2: pose rows k in [20,326) ----
    #pragma unroll 2
    for (int k = NBb; k < KTOT; k++) {
        float4 nb0, nb1;
        if (k + 1 < KTOT) {
            nb0 = *(const float4*)(g_B + (k + 1) * BW + cb0);
            nb1 = *(const float4*)(g_B + (k + 1) * BW + cb1);
        }
        const ull* A2 = (const ull*)(As + k * 32) + ri * 4;
        ull a[4] = {A2[0], A2[1], A2[2], A2[3]};
        ull B8[8] = {pack2(b0.x,b0.x), pack2(b0.y,b0.y), pack2(b0.z,b0.z), pack2(b0.w,b0.w),
                     pack2(b1.x,b1.x), pack2(b1.y,b1.y), pack2(b1.z,b1.z), pack2(b1.w,b1.w)};
        #pragma unroll
        for (int p = 0; p < 4; p++)
            #pragma unroll
            for (int q = 0; q < 8; q++) fma2(acc[p][q], a[p], B8[q]);
        b0 = nb0; b1 = nb1;
    }

    // ---- epilogue: v_posed ----
    #pragma unroll
    for (int p = 0; p < 4; p++) {
        int ra = nb + 8 * ri + 2 * p, rb = ra + 1;
        #pragma unroll
        for (int q = 0; q < 8; q++) {
            int c = (q < 4) ? cb0 + q : cb1 + q - 4;
            if (c < VC) {
                float lo, hi;
                unpack2(acc[p][q], lo, hi);
                g_vposed[(size_t)ra * VC + c] = lo;
                g_vposed[(size_t)rb * VC + c] = hi;
            }
        }
    }
}

// ---------------- K4: J-regressor reduce (AoS input, 2 n packed) --------------
__global__ void __launch_bounds__(128) k_reduce_part(int mode, const float* __restrict__ Xext) {
    const float* X = mode ? Xext : g_vshaped;
    const int ch = blockIdx.x;          // 8 chunks
    const int np = blockIdx.y;          // 256 n-pairs
    const int w = threadIdx.x >> 5, lane = threadIdx.x & 31;
    const int j0 = w * 9;
    const int nj = (Jj - j0 < 9) ? (Jj - j0) : 9;

    ull acc[9][3];
    #pragma unroll
    for (int jj = 0; jj < 9; jj++)
        #pragma unroll
        for (int c = 0; c < 3; c++) acc[jj][c] = 0ull;

    int v0 = ch * 487, v1 = v0 + 487; if (v1 > Vv) v1 = Vv;
    const float* Xa = X + (size_t)(2 * np)     * VC;
    const float* Xb = X + (size_t)(2 * np + 1) * VC;

    for (int v = v0 + lane; v < v1; v += 32) {
        float jr[9];
        #pragma unroll
        for (int jj = 0; jj < 9; jj++) jr[jj] = (jj < nj) ? g_JrT[(j0 + jj) * Vv + v] : 0.f;
        ull xv[3];
        #pragma unroll
        for (int c = 0; c < 3; c++) xv[c] = pack2(Xa[3 * v + c], Xb[3 * v + c]);
        #pragma unroll
        for (int jj = 0; jj < 9; jj++) {
            ull jr2 = pack2(jr[jj], jr[jj]);
            #pragma unroll
            for (int c = 0; c < 3; c++) fma2(acc[jj][c], jr2, xv[c]);
        }
    }

    #pragma unroll
    for (int jj = 0; jj < 9; jj++) {
        if (jj >= nj) break;
        #pragma unroll
        for (int c = 0; c < 3; c++) {
            float lo, hi;
            unpack2(acc[jj][c], lo, hi);
            #pragma unroll
            for (int o = 16; o; o >>= 1) {
                lo += __shfl_xor_sync(0xffffffffu, lo, o);
                hi += __shfl_xor_sync(0xffffffffu, hi, o);
            }
            if (lane == 0) {
                g_part[(size_t)((2 * np)     * 8 + ch) * NJ3 + (j0 + jj) * 3 + c] = lo;
                g_part[(size_t)((2 * np + 1) * 8 + ch) * NJ3 + (j0 + jj) * 3 + c] = hi;
            }
        }
    }
}

__global__ void k_reduce_final(int mode, float* __restrict__ dstext) {
    int i = blockIdx.x * 128 + threadIdx.x;
    if (i >= Nn * NJ3) return;
    int n = i / NJ3;
    float s = 0.0f;
    #pragma unroll
    for (int ch = 0; ch < 8; ch++) s += g_part[(size_t)(n * 8 + ch) * NJ3 + (i % NJ3)];
    if (mode == 0) g_Jp[i] = s; else dstext[i] = s;
}

// ---------------- K5: kinematic chain — warp per n, G in shared ---------------
__global__ void __launch_bounds__(256) k_kin(const float* __restrict__ rs,
                                             const float* __restrict__ scales,
                                             const int* __restrict__ parents) {
    __shared__ float sG[8][Jj][12];
    const int w = threadIdx.x >> 5, lane = threadIdx.x & 31;
    const int n = blockIdx.x * 8 + w;
    if (n >= Nn) return;
    const float* R  = rs + (size_t)n * Jj * 9;
    const float* Jp = g_Jp + n * NJ3;
    const float* sc = scales + n * NJ3;
    const int a = lane >> 2, u = lane & 3;

    if (lane < 12) sG[w][0][lane] = (u < 3) ? R[a * 3 + u] : Jp[a];
    __syncwarp();

    for (int i = 1; i < Jj; i++) {
        int p = parents[i];
        float val = 0.f;
        if (lane < 12) {
            float gp0 = sG[w][p][a * 4 + 0];
            float gp1 = sG[w][p][a * 4 + 1];
            float gp2 = sG[w][p][a * 4 + 2];
            if (u < 3) {
                float si = sc[i * 3 + u];
                val = gp0 * (R[i * 9 + 0 + u] * si / sc[p * 3 + 0])
                    + gp1 * (R[i * 9 + 3 + u] * si / sc[p * 3 + 1])
                    + gp2 * (R[i * 9 + 6 + u] * si / sc[p * 3 + 2]);
            } else {
                float t0 = Jp[i * 3 + 0] - Jp[p * 3 + 0];
                float t1 = Jp[i * 3 + 1] - Jp[p * 3 + 1];
                float t2 = Jp[i * 3 + 2] - Jp[p * 3 + 2];
                val = gp0 * t0 + gp1 * t1 + gp2 * t2 + sG[w][p][a * 4 + 3];
            }
        }
        __syncwarp();
        if (lane < 12) sG[w][i][lane] = val;
        __syncwarp();
    }

    float* gA = g_A + (size_t)n * Jj * 12;
    for (int idx = lane; idx < Jj * 12; idx += 32) {
        int i = idx / 12, e = idx - i * 12;
        int aa = e >> 2, uu = e & 3;
        float val;
        if (uu < 3) val = sG[w][i][aa * 4 + uu];
        else {
            float g0 = sG[w][i][aa * 4 + 0], g1 = sG[w][i][aa * 4 + 1], g2 = sG[w][i][aa * 4 + 2];
            val = sG[w][i][aa * 4 + 3] - (g0 * Jp[i * 3 + 0] + g1 * Jp[i * 3 + 1] + g2 * Jp[i * 3 + 2]);
        }
        gA[idx] = val;
    }
}

// ---------------- K6: skinning (f32x2, AoS in/out) -----------------------------
__global__ void __launch_bounds__(128) k_skin(const float* __restrict__ trans, float* __restrict__ out) {
    __shared__ __align__(16) float sA[2 * Jj * 12];
    const int t = threadIdx.x;
    const int nb = blockIdx.y * 2;
    for (int i = t; i < 2 * Jj * 12; i += 128) sA[i] = g_A[(size_t)nb * Jj * 12 + i];
    __syncthreads();
    const ull* sA2 = (const ull*)sA;
    const int vb = blockIdx.x * 512 + t;

    ull T[2][4][6];
    #pragma unroll
    for (int nl = 0; nl < 2; nl++)
        #pragma unroll
        for (int u = 0; u < 4; u++)
            #pragma unroll
            for (int e = 0; e < 6; e++) T[nl][u][e] = 0ull;

    for (int j = 0; j < Jj; j++) {
        ull W[4];
        #pragma unroll
        for (int u = 0; u < 4; u++) {
            int v = vb + 128 * u;
            float w = (v < Vv) ? g_WtT[j * Vv + v] : 0.f;
            W[u] = pack2(w, w);
        }
        #pragma unroll
        for (int nl = 0; nl < 2; nl++) {
            #pragma unroll
            for (int e = 0; e < 6; e++) {
                ull a2 = sA2[nl * 210 + j * 6 + e];
                #pragma unroll
                for (int u = 0; u < 4; u++) fma2(T[nl][u][e], W[u], a2);
            }
        }
    }

    #pragma unroll
    for (int nl = 0; nl < 2; nl++) {
        int n = nb + nl;
        float t0 = trans[n * 3 + 0], t1 = trans[n * 3 + 1], t2 = trans[n * 3 + 2];
        const float* vp = g_vposed + (size_t)n * VC;
        #pragma unroll
        for (int u = 0; u < 4; u++) {
            int v = vb + 128 * u;
            if (v < Vv) {
                float e[12];
                #pragma unroll
                for (int p = 0; p < 6; p++) unpack2(T[nl][u][p], e[2 * p], e[2 * p + 1]);
                float x = vp[3 * v], y = vp[3 * v + 1], z = vp[3 * v + 2];
                out[(size_t)n * VC + 3 * v + 0] = fmaf(e[0], x, fmaf(e[1], y, fmaf(e[2],  z, e[3])))  + t0;
                out[(size_t)n * VC + 3 * v + 1] = fmaf(e[4], x, fmaf(e[5], y, fmaf(e[6],  z, e[7])))  + t1;
                out[(size_t)n * VC + 3 * v + 2] = fmaf(e[8], x, fmaf(e[9], y, fmaf(e[10], z, e[11]))) + t2;
            }
        }
    }
}

// ---------------- launch -------------------------------------------------------
extern "C" void kernel_launch(void* const* d_in, const int* in_sizes, int n_in,
                              void* d_out, int out_size) {
    const float* beta     = (const float*)d_in[0];
    const float* theta    = (const float*)d_in[1];
    const float* scales   = (const float*)d_in[2];
    const float* deform   = (const float*)d_in[3];
    const float* trans    = (const float*)d_in[4];
    const float* vtemp    = (const float*)d_in[5];
    const float* sdirs    = (const float*)d_in[6];
    const float* pdirs    = (const float*)d_in[7];
    const float* Jr       = (const float*)d_in[8];
    const float* Wt       = (const float*)d_in[9];
    const int*   parents  = (const int*)d_in[10];
    float* out = (float*)d_out;

    const int prep_tot = KTOT * BW + 2 * Jj * Vv;
    k_prep<<<(prep_tot + 255) / 256, 256>>>(sdirs, pdirs, Jr, Wt);
    k_rodrigues<<<(Nn * Jj + 127) / 128, 128>>>(theta, out + RS_OFF);
    k_gemm<<<dim3(23, 16), 256>>>(beta, vtemp, deform);
    k_reduce_part<<<dim3(8, 256), 128>>>(0, nullptr);
    k_reduce_final<<<(Nn * NJ3 + 127) / 128, 128>>>(0, nullptr);
    k_kin<<<64, 256>>>(out + RS_OFF, scales, parents);
    k_skin<<<dim3(8, 256), 128>>>(trans, out);
    k_reduce_part<<<dim3(8, 256), 128>>>(1, out);
    k_reduce_final<<<(Nn * NJ3 + 127) / 128, 128>>>(1, out + JOINTS_OFF);
}